// round 3
// baseline (speedup 1.0000x reference)
#include <cuda_runtime.h>
#include <cuda_bf16.h>
#include <math.h>

// Problem constants
#define BB   8
#define NN   512
#define HID  512
#define HH   8
#define DD   64
#define EE   32
#define NCT  32
#define UU   16   // edge-MLP hidden = 2*H = 16
// SCALE = sqrt(64) = 8 -> multiply by 0.125f

#define M_TOT (BB * NN)          // 4096
#define OUT_PART (BB * NN * HID) // 2097152
#define MEAN_ELEMS (BB * NN * NN)// 2097152
#define PAIRS ((long)BB * NN * NN)

// ---------------- scratch (device globals; no allocation) ----------------
__device__ float g_q[BB * NN * HID];
__device__ float g_k[BB * NN * HID];
__device__ float g_v[BB * NN * HID];
__device__ float g_ao[BB * NN * HID];
__device__ float g_eb[BB * NN * NN * HH];   // (B, N, N, H)
__device__ int   g_mask_mode;               // 0 = 4-byte elems, 1 = 1-byte elems

// ---------------- mask dtype detection ----------------
// block_mask is Bernoulli(0.5) over 2M elements. Scan 256 words:
//  - float32 bools: words in {0, 0x3F800000}
//  - int32 bools:   words in {0, 1}
//  - packed uint8:  words contain bytes in positions 1..3 w.h.p.
__global__ void detect_mask_kernel(const unsigned int* __restrict__ bm) {
    bool sawFloat = false, sawHigh = false;
    for (int i = 0; i < 256; i++) {
        unsigned int w = bm[i];
        if (w == 0x3F800000u) sawFloat = true;
        else if (w & 0xFFFFFF00u) sawHigh = true;
    }
    g_mask_mode = (!sawFloat && sawHigh) ? 1 : 0;
}

// ---------------- zero kernel ----------------
__global__ void zero_kernel(float* __restrict__ p, int n) {
    int i = blockIdx.x * blockDim.x + threadIdx.x;
    if (i < n) p[i] = 0.0f;
}

// ---------------- SGEMM: C[M,512] = X[M,512] @ W[512,512] + bias (+ct) ----
__global__ __launch_bounds__(256) void gemm512_kernel(
    const float* __restrict__ X, const float* __restrict__ W,
    const float* __restrict__ bias,
    const float* __restrict__ ct_emb, const int* __restrict__ ct_idx,
    float* __restrict__ C, int add_ct)
{
    __shared__ float As[64][16];
    __shared__ float Bs[16][64];

    const int tid = threadIdx.x;
    const int n0 = blockIdx.x * 64;
    const int m0 = blockIdx.y * 64;
    const int tx = tid & 15;
    const int ty = tid >> 4;

    const int lmA  = tid >> 2;          // 0..63 (row of A)
    const int lk4  = (tid & 3) * 4;     // k quad
    const int lkB  = tid >> 4;          // 0..15 (row of B)
    const int ln4  = (tid & 15) * 4;    // n quad

    float acc[4][4];
#pragma unroll
    for (int i = 0; i < 4; i++)
#pragma unroll
        for (int j = 0; j < 4; j++) acc[i][j] = 0.0f;

    for (int k0 = 0; k0 < 512; k0 += 16) {
        float4 av = *(const float4*)&X[(size_t)(m0 + lmA) * 512 + k0 + lk4];
        float4 bv = *(const float4*)&W[(size_t)(k0 + lkB) * 512 + n0 + ln4];
        *(float4*)&As[lmA][lk4] = av;
        *(float4*)&Bs[lkB][ln4] = bv;
        __syncthreads();
#pragma unroll
        for (int kk = 0; kk < 16; kk++) {
            float a[4], b[4];
#pragma unroll
            for (int i = 0; i < 4; i++) a[i] = As[ty + 16 * i][kk];
#pragma unroll
            for (int j = 0; j < 4; j++) b[j] = Bs[kk][tx + 16 * j];
#pragma unroll
            for (int i = 0; i < 4; i++)
#pragma unroll
                for (int j = 0; j < 4; j++) acc[i][j] += a[i] * b[j];
        }
        __syncthreads();
    }

#pragma unroll
    for (int i = 0; i < 4; i++) {
        int row = m0 + ty + 16 * i;
        int b_of_row = row >> 9;  // row / N
#pragma unroll
        for (int j = 0; j < 4; j++) {
            int col = n0 + tx + 16 * j;
            float v = acc[i][j] + bias[col];
            if (add_ct) v += ct_emb[(size_t)ct_idx[b_of_row] * 512 + col];
            C[(size_t)row * 512 + col] = v;
        }
    }
}

// ---------------- edge MLP: eb = elu(EF @ W1 + b1) @ W2 + b2 --------------
__global__ __launch_bounds__(256) void edge_mlp_kernel(
    const float* __restrict__ ef, const float* __restrict__ W1,
    const float* __restrict__ b1, const float* __restrict__ W2,
    const float* __restrict__ b2, float* __restrict__ eb)
{
    __shared__ float w1_s[EE][UU];   // 32 x 16
    __shared__ float w2_s[UU][HH];   // 16 x 8
    __shared__ float b1_s[UU];
    __shared__ float b2_s[HH];

    const int tid = threadIdx.x;
    for (int i = tid; i < EE * UU; i += 256) ((float*)w1_s)[i] = W1[i];
    if (tid < UU * HH) ((float*)w2_s)[tid] = W2[tid];
    if (tid < UU) b1_s[tid] = b1[tid];
    if (tid < HH) b2_s[tid] = b2[tid];
    __syncthreads();

    const long p = (long)blockIdx.x * 256 + tid;

    float e[EE];
#pragma unroll
    for (int i = 0; i < EE / 4; i++) {
        float4 v = *(const float4*)&ef[p * EE + i * 4];
        e[i * 4 + 0] = v.x; e[i * 4 + 1] = v.y;
        e[i * 4 + 2] = v.z; e[i * 4 + 3] = v.w;
    }

    float h[UU];
#pragma unroll
    for (int u = 0; u < UU; u++) h[u] = b1_s[u];
#pragma unroll
    for (int k = 0; k < EE; k++) {
        float ek = e[k];
#pragma unroll
        for (int u = 0; u < UU; u++) h[u] += ek * w1_s[k][u];
    }
#pragma unroll
    for (int u = 0; u < UU; u++) {
        float xv = h[u];
        h[u] = (xv > 0.0f) ? xv : expm1f(xv);
    }

    float o[HH];
#pragma unroll
    for (int oo = 0; oo < HH; oo++) o[oo] = b2_s[oo];
#pragma unroll
    for (int u = 0; u < UU; u++) {
        float hv = h[u];
#pragma unroll
        for (int oo = 0; oo < HH; oo++) o[oo] += hv * w2_s[u][oo];
    }

    *(float4*)&eb[p * HH + 0] = make_float4(o[0], o[1], o[2], o[3]);
    *(float4*)&eb[p * HH + 4] = make_float4(o[4], o[5], o[6], o[7]);
}

// ---------------- fused attention per (b, h, 16-row tile) -----------------
__global__ __launch_bounds__(256) void attn_kernel(
    const void* __restrict__ block_mask_raw,
    const void* __restrict__ pad_mask_raw,
    const float* __restrict__ ct_bias, const int* __restrict__ ct_idx,
    float* __restrict__ mean_out)
{
    extern __shared__ float smem[];
    float* q_s = smem;                 // 1024
    float* S   = smem + 1024;          // 8192
    float* kv  = smem + 1024 + 8192;   // 16640 (256*65)

    __shared__ unsigned char padi_s[16];
    __shared__ unsigned char padj_s[512];

    const int tid = threadIdx.x;
    const int idx = blockIdx.x;
    const int h  = idx & 7;
    const int it = (idx >> 3) & 31;
    const int b  = idx >> 8;
    const int i0 = it * 16;
    const int mode = g_mask_mode;   // 0 = 4-byte mask elems, 1 = 1-byte

    const unsigned int*  bm_w = (const unsigned int*)block_mask_raw;
    const unsigned char* bm_b = (const unsigned char*)block_mask_raw;
    const unsigned int*  pm_w = (const unsigned int*)pad_mask_raw;
    const unsigned char* pm_b = (const unsigned char*)pad_mask_raw;

    // load q tile (16 rows x 64)
    {
        int r = tid >> 4, c4 = (tid & 15) * 4;
        float4 v = *(const float4*)&g_q[((size_t)(b * NN + i0 + r)) * HID + h * DD + c4];
        *(float4*)&q_s[r * 64 + c4] = v;
    }
    // pad flags
    if (tid < 16) {
        int gi = b * NN + i0 + tid;
        padi_s[tid] = mode ? (pm_b[gi] != 0) : (pm_w[gi] != 0u);
    }
    for (int j = tid; j < 512; j += 256) {
        int gj = b * NN + j;
        padj_s[j] = mode ? (pm_b[gj] != 0) : (pm_w[gj] != 0u);
    }
    const float ctb = ct_bias[(size_t)ct_idx[b] * HH + h];
    __syncthreads();

    // prefill S with bias / -inf
    for (int x = tid; x < 16 * 512; x += 256) {
        int r = x >> 9, j = x & 511;
        size_t gi = (size_t)(b * NN + i0 + r);
        bool bmv = mode ? (bm_b[gi * NN + j] != 0) : (bm_w[gi * NN + j] != 0u);
        bool masked = bmv || padi_s[r] || padj_s[j];
        S[r * 512 + j] = masked ? -INFINITY
                                : (ctb + g_eb[(gi * NN + j) * HH + h]);
    }
    __syncthreads();

    // ---- QK^T ----
    {
        const int jx = tid & 63;
        const int ry = tid >> 6;
        for (int jt = 0; jt < 2; jt++) {
            for (int i = tid; i < 4096; i += 256) {
                int row = i >> 4, c4 = (i & 15) * 4;
                float4 v = *(const float4*)&g_k[((size_t)(b * NN + jt * 256 + row)) * HID + h * DD + c4];
                kv[row * 65 + c4 + 0] = v.x; kv[row * 65 + c4 + 1] = v.y;
                kv[row * 65 + c4 + 2] = v.z; kv[row * 65 + c4 + 3] = v.w;
            }
            __syncthreads();
            float qacc[4][4];
#pragma unroll
            for (int i = 0; i < 4; i++)
#pragma unroll
                for (int j = 0; j < 4; j++) qacc[i][j] = 0.0f;
            for (int d = 0; d < 64; d++) {
                float qa[4], kb[4];
#pragma unroll
                for (int ri = 0; ri < 4; ri++) qa[ri] = q_s[(ry + 4 * ri) * 64 + d];
#pragma unroll
                for (int ji = 0; ji < 4; ji++) kb[ji] = kv[(jx + 64 * ji) * 65 + d];
#pragma unroll
                for (int ri = 0; ri < 4; ri++)
#pragma unroll
                    for (int ji = 0; ji < 4; ji++) qacc[ri][ji] += qa[ri] * kb[ji];
            }
#pragma unroll
            for (int ri = 0; ri < 4; ri++)
#pragma unroll
                for (int ji = 0; ji < 4; ji++)
                    S[(ry + 4 * ri) * 512 + jt * 256 + jx + 64 * ji] += qacc[ri][ji] * 0.125f;
            __syncthreads();
        }
    }

    // ---- softmax + mean accumulation ----
    {
        const int warp = tid >> 5, lane = tid & 31;
        for (int r = warp; r < 16; r += 8) {
            float vals[16];
            float m = -INFINITY;
#pragma unroll
            for (int c = 0; c < 16; c++) {
                vals[c] = S[r * 512 + lane + 32 * c];
                m = fmaxf(m, vals[c]);
            }
#pragma unroll
            for (int off = 16; off; off >>= 1)
                m = fmaxf(m, __shfl_xor_sync(0xffffffffu, m, off));
            float sum = 0.0f;
            if (isinf(m) && m < 0.0f) {
#pragma unroll
                for (int c = 0; c < 16; c++) vals[c] = 0.0f;
            } else {
#pragma unroll
                for (int c = 0; c < 16; c++) { vals[c] = __expf(vals[c] - m); sum += vals[c]; }
            }
#pragma unroll
            for (int off = 16; off; off >>= 1)
                sum += __shfl_xor_sync(0xffffffffu, sum, off);
            float inv = (sum > 0.0f) ? (1.0f / sum) : 0.0f;
            size_t mrow = ((size_t)(b * NN + i0 + r)) * NN;
#pragma unroll
            for (int c = 0; c < 16; c++) {
                float pv = vals[c] * inv;
                S[r * 512 + lane + 32 * c] = pv;
                atomicAdd(&mean_out[mrow + lane + 32 * c], pv * 0.125f);
            }
        }
    }
    __syncthreads();

    // ---- P @ V ----
    {
        const int g  = tid >> 6;        // 0..3 j-split group
        const int t  = tid & 63;
        const int rx = t >> 4;          // 0..3
        const int dx = t & 15;          // 0..15
        float oacc[4][4];
#pragma unroll
        for (int i = 0; i < 4; i++)
#pragma unroll
            for (int j = 0; j < 4; j++) oacc[i][j] = 0.0f;

        for (int jt = 0; jt < 2; jt++) {
            for (int i = tid; i < 4096; i += 256) {
                int row = i >> 4, c4 = (i & 15) * 4;
                float4 v = *(const float4*)&g_v[((size_t)(b * NN + jt * 256 + row)) * HID + h * DD + c4];
                kv[row * 65 + c4 + 0] = v.x; kv[row * 65 + c4 + 1] = v.y;
                kv[row * 65 + c4 + 2] = v.z; kv[row * 65 + c4 + 3] = v.w;
            }
            __syncthreads();
            for (int jj = 0; jj < 64; jj++) {
                int j = g * 64 + jj;
                float pr[4], vv[4];
#pragma unroll
                for (int ri = 0; ri < 4; ri++) pr[ri] = S[(rx + 4 * ri) * 512 + jt * 256 + j];
#pragma unroll
                for (int di = 0; di < 4; di++) vv[di] = kv[j * 65 + dx + 16 * di];
#pragma unroll
                for (int ri = 0; ri < 4; ri++)
#pragma unroll
                    for (int di = 0; di < 4; di++) oacc[ri][di] += pr[ri] * vv[di];
            }
            __syncthreads();
        }

        float* red = kv;  // 4*16*64 = 4096 floats
#pragma unroll
        for (int ri = 0; ri < 4; ri++)
#pragma unroll
            for (int di = 0; di < 4; di++)
                red[(g * 16 + rx + 4 * ri) * 64 + dx + 16 * di] = oacc[ri][di];
        __syncthreads();
        for (int x = tid; x < 1024; x += 256) {
            int r = x >> 6, dc = x & 63;
            float v = red[r * 64 + dc] + red[1024 + r * 64 + dc]
                    + red[2048 + r * 64 + dc] + red[3072 + r * 64 + dc];
            g_ao[((size_t)(b * NN + i0 + r)) * HID + h * DD + dc] = v;
        }
    }
}

// ---------------- launch ----------------
extern "C" void kernel_launch(void* const* d_in, const int* in_sizes, int n_in,
                              void* d_out, int out_size)
{
    const float* x    = (const float*)d_in[0];
    const int*   ct   = (const int*)d_in[1];
    const float* ef   = (const float*)d_in[2];
    const void*  block_mask = d_in[3];
    const void*  pad_mask   = d_in[4];
    const float* Wq = (const float*)d_in[5];
    const float* bq = (const float*)d_in[6];
    const float* Wk = (const float*)d_in[7];
    const float* bk = (const float*)d_in[8];
    const float* Wv = (const float*)d_in[9];
    const float* bv = (const float*)d_in[10];
    const float* Wo = (const float*)d_in[11];
    const float* bo = (const float*)d_in[12];
    const float* We1 = (const float*)d_in[13];
    const float* be1 = (const float*)d_in[14];
    const float* We2 = (const float*)d_in[15];
    const float* be2 = (const float*)d_in[16];
    const float* ct_key  = (const float*)d_in[17];
    const float* ct_bias = (const float*)d_in[18];

    float* out_main = (float*)d_out;
    float* out_mean = out_main + OUT_PART;

    float *q_p, *k_p, *v_p, *ao_p, *eb_p;
    cudaGetSymbolAddress((void**)&q_p,  g_q);
    cudaGetSymbolAddress((void**)&k_p,  g_k);
    cudaGetSymbolAddress((void**)&v_p,  g_v);
    cudaGetSymbolAddress((void**)&ao_p, g_ao);
    cudaGetSymbolAddress((void**)&eb_p, g_eb);

    const int attn_smem = (1024 + 8192 + 256 * 65) * sizeof(float);
    cudaFuncSetAttribute(attn_kernel, cudaFuncAttributeMaxDynamicSharedMemorySize, attn_smem);

    // 0) detect mask element width (bool serialized as f32/i32/u8)
    detect_mask_kernel<<<1, 1>>>((const unsigned int*)block_mask);

    // 1) zero the mean output (accumulated via atomics)
    zero_kernel<<<(MEAN_ELEMS + 255) / 256, 256>>>(out_mean, MEAN_ELEMS);

    // 2) projections
    dim3 ggrid(512 / 64, M_TOT / 64);
    gemm512_kernel<<<ggrid, 256>>>(x, Wq, bq, ct_key, ct, q_p, 0);
    gemm512_kernel<<<ggrid, 256>>>(x, Wk, bk, ct_key, ct, k_p, 1);  // fuses +ct_key
    gemm512_kernel<<<ggrid, 256>>>(x, Wv, bv, ct_key, ct, v_p, 0);

    // 3) edge MLP (hidden = 16)
    edge_mlp_kernel<<<(int)(PAIRS / 256), 256>>>(ef, We1, be1, We2, be2, eb_p);

    // 4) fused attention
    attn_kernel<<<BB * 32 * HH, 256, attn_smem>>>(block_mask, pad_mask, ct_bias, ct, out_mean);

    // 5) output projection
    gemm512_kernel<<<ggrid, 256>>>(ao_p, Wo, bo, ct_key, ct, out_main, 0);
}

// round 4
// speedup vs baseline: 1.8437x; 1.8437x over previous
#include <cuda_runtime.h>
#include <cuda_fp16.h>
#include <math.h>

// Problem constants
#define BB   8
#define NN   512
#define HID  512
#define HH   8
#define DD   64
#define EE   32
#define UU   16   // edge-MLP hidden = 2*H = 16

#define M_TOT (BB * NN)          // 4096
#define OUT_PART (BB * NN * HID) // 2097152
#define MEAN_ELEMS (BB * NN * NN)// 2097152
#define PAIRS ((long)BB * NN * NN)
#define NSQ  (NN * NN)           // 262144 = 2^18

// ---------------- scratch (device globals; no allocation) ----------------
__device__ float g_q[BB * NN * HID];
__device__ float g_k[BB * NN * HID];
__device__ float g_v[BB * NN * HID];
__device__ float g_ao[BB * NN * HID];
__device__ float g_eb[BB * HH * NN * NN];   // (B, H, N, N)  <- transposed layout
__device__ int   g_mask_mode;               // 0 = 4-byte elems, 1 = 1-byte elems

// ---------------- mask dtype detection (parallel) ----------------
__global__ void detect_mask_kernel(const unsigned int* __restrict__ bm) {
    __shared__ int sFloat, sHigh;
    if (threadIdx.x == 0) { sFloat = 0; sHigh = 0; }
    __syncthreads();
    unsigned int w = bm[threadIdx.x];
    if (w == 0x3F800000u) sFloat = 1;          // benign race
    else if (w & 0xFFFFFF00u) sHigh = 1;
    __syncthreads();
    if (threadIdx.x == 0) g_mask_mode = (!sFloat && sHigh) ? 1 : 0;
}

// ---------------- zero kernel ----------------
__global__ void zero_kernel(float* __restrict__ p, int n) {
    int i = blockIdx.x * blockDim.x + threadIdx.x;
    if (i < n) p[i] = 0.0f;
}

// ============ fp16 tensor-core GEMM: C[M,512] = X@W + bias (+ct) =========
// BM=128, BN=64, BK=32, 256 threads (8 warps as 4m x 2n), warp tile 32x32.
#define GBM 128
#define GBN 64
#define GBK 32

__device__ __forceinline__ void ldmatrix_x4(unsigned& r0, unsigned& r1,
                                            unsigned& r2, unsigned& r3,
                                            unsigned addr) {
    asm volatile("ldmatrix.sync.aligned.m8n8.x4.shared.b16 {%0,%1,%2,%3}, [%4];"
                 : "=r"(r0), "=r"(r1), "=r"(r2), "=r"(r3) : "r"(addr));
}
__device__ __forceinline__ void ldmatrix_x4_trans(unsigned& r0, unsigned& r1,
                                                  unsigned& r2, unsigned& r3,
                                                  unsigned addr) {
    asm volatile("ldmatrix.sync.aligned.m8n8.x4.trans.shared.b16 {%0,%1,%2,%3}, [%4];"
                 : "=r"(r0), "=r"(r1), "=r"(r2), "=r"(r3) : "r"(addr));
}
__device__ __forceinline__ void mma16816(float* c, const unsigned* a,
                                         unsigned b0, unsigned b1) {
    asm volatile(
        "mma.sync.aligned.m16n8k16.row.col.f32.f16.f16.f32 "
        "{%0,%1,%2,%3}, {%4,%5,%6,%7}, {%8,%9}, {%0,%1,%2,%3};"
        : "+f"(c[0]), "+f"(c[1]), "+f"(c[2]), "+f"(c[3])
        : "r"(a[0]), "r"(a[1]), "r"(a[2]), "r"(a[3]), "r"(b0), "r"(b1));
}

__global__ __launch_bounds__(256) void gemm_f16_kernel(
    const float* __restrict__ X, const float* __restrict__ W,
    const float* __restrict__ bias,
    const float* __restrict__ ct_emb, const int* __restrict__ ct_idx,
    float* __restrict__ C, int add_ct)
{
    __shared__ __half As[GBM][GBK + 8];   // stride 40 halves = 80B (ldmatrix conflict-free)
    __shared__ __half Bs[GBK][GBN + 8];   // stride 72 halves = 144B

    const int tid  = threadIdx.x;
    const int m0   = blockIdx.y * GBM;
    const int n0   = blockIdx.x * GBN;
    const int warp = tid >> 5, lane = tid & 31;
    const int wm   = warp >> 1, wn = warp & 1;

    float acc[2][4][4];
#pragma unroll
    for (int i = 0; i < 2; i++)
#pragma unroll
        for (int j = 0; j < 4; j++)
#pragma unroll
            for (int f = 0; f < 4; f++) acc[i][j][f] = 0.0f;

    for (int k0 = 0; k0 < 512; k0 += GBK) {
        // load X tile (128x32 fp32 -> fp16)
#pragma unroll
        for (int l = 0; l < 4; l++) {
            int lin = tid + l * 256;
            int row = lin >> 3, q = (lin & 7) * 4;
            float4 v = *(const float4*)&X[(size_t)(m0 + row) * 512 + k0 + q];
            *(__half2*)&As[row][q]     = __float22half2_rn(make_float2(v.x, v.y));
            *(__half2*)&As[row][q + 2] = __float22half2_rn(make_float2(v.z, v.w));
        }
        // load W tile (32x64 fp32 -> fp16)
#pragma unroll
        for (int l = 0; l < 2; l++) {
            int lin = tid + l * 256;
            int kr = lin >> 4, q = (lin & 15) * 4;
            float4 v = *(const float4*)&W[(size_t)(k0 + kr) * 512 + n0 + q];
            *(__half2*)&Bs[kr][q]     = __float22half2_rn(make_float2(v.x, v.y));
            *(__half2*)&Bs[kr][q + 2] = __float22half2_rn(make_float2(v.z, v.w));
        }
        __syncthreads();

#pragma unroll
        for (int s = 0; s < 2; s++) {
            unsigned a[2][4], b[2][4];
#pragma unroll
            for (int mi = 0; mi < 2; mi++) {
                unsigned addr = (unsigned)__cvta_generic_to_shared(
                    &As[wm * 32 + mi * 16 + (lane & 15)][s * 16 + (lane >> 4) * 8]);
                ldmatrix_x4(a[mi][0], a[mi][1], a[mi][2], a[mi][3], addr);
            }
#pragma unroll
            for (int p = 0; p < 2; p++) {
                unsigned addr = (unsigned)__cvta_generic_to_shared(
                    &Bs[s * 16 + ((lane >> 3) & 1) * 8 + (lane & 7)]
                       [wn * 32 + p * 16 + (lane >> 4) * 8]);
                ldmatrix_x4_trans(b[p][0], b[p][1], b[p][2], b[p][3], addr);
            }
#pragma unroll
            for (int mi = 0; mi < 2; mi++)
#pragma unroll
                for (int nj = 0; nj < 4; nj++) {
                    int p = nj >> 1, hsel = nj & 1;
                    mma16816(acc[mi][nj], a[mi], b[p][2 * hsel], b[p][2 * hsel + 1]);
                }
        }
        __syncthreads();
    }

    // epilogue
#pragma unroll
    for (int mi = 0; mi < 2; mi++) {
        int row = m0 + wm * 32 + mi * 16 + (lane >> 2);
        int b_of_row = row >> 9;
        const float* cte = add_ct ? &ct_emb[(size_t)ct_idx[b_of_row] * 512] : nullptr;
        const float* cte2 = add_ct ? &ct_emb[(size_t)ct_idx[(row + 8) >> 9] * 512] : nullptr;
#pragma unroll
        for (int nj = 0; nj < 4; nj++) {
            int col = n0 + wn * 32 + nj * 8 + (lane & 3) * 2;
            float b0 = bias[col], b1 = bias[col + 1];
            float c0 = acc[mi][nj][0] + b0, c1 = acc[mi][nj][1] + b1;
            float c2 = acc[mi][nj][2] + b0, c3 = acc[mi][nj][3] + b1;
            if (add_ct) {
                c0 += cte[col];  c1 += cte[col + 1];
                c2 += cte2[col]; c3 += cte2[col + 1];
            }
            *(float2*)&C[(size_t)row * 512 + col]       = make_float2(c0, c1);
            *(float2*)&C[(size_t)(row + 8) * 512 + col] = make_float2(c2, c3);
        }
    }
}

// ---------------- edge MLP: eb = elu(EF @ W1 + b1) @ W2 + b2 --------------
// Writes TRANSPOSED layout (B, H, N, N) for coalesced attention reads.
__global__ __launch_bounds__(256) void edge_mlp_kernel(
    const float* __restrict__ ef, const float* __restrict__ W1,
    const float* __restrict__ b1, const float* __restrict__ W2,
    const float* __restrict__ b2, float* __restrict__ eb)
{
    __shared__ float w1_s[EE][UU];
    __shared__ float w2_s[UU][HH];
    __shared__ float b1_s[UU];
    __shared__ float b2_s[HH];

    const int tid = threadIdx.x;
    for (int i = tid; i < EE * UU; i += 256) ((float*)w1_s)[i] = W1[i];
    if (tid < UU * HH) ((float*)w2_s)[tid] = W2[tid];
    if (tid < UU) b1_s[tid] = b1[tid];
    if (tid < HH) b2_s[tid] = b2[tid];
    __syncthreads();

    const long p = (long)blockIdx.x * 256 + tid;

    float e[EE];
#pragma unroll
    for (int i = 0; i < EE / 4; i++) {
        float4 v = *(const float4*)&ef[p * EE + i * 4];
        e[i * 4 + 0] = v.x; e[i * 4 + 1] = v.y;
        e[i * 4 + 2] = v.z; e[i * 4 + 3] = v.w;
    }

    float h[UU];
#pragma unroll
    for (int u = 0; u < UU; u++) h[u] = b1_s[u];
#pragma unroll
    for (int k = 0; k < EE; k++) {
        float ek = e[k];
#pragma unroll
        for (int u = 0; u < UU; u++) h[u] += ek * w1_s[k][u];
    }
#pragma unroll
    for (int u = 0; u < UU; u++) {
        float xv = h[u];
        h[u] = (xv > 0.0f) ? xv : expm1f(xv);
    }

    float o[HH];
#pragma unroll
    for (int oo = 0; oo < HH; oo++) o[oo] = b2_s[oo];
#pragma unroll
    for (int u = 0; u < UU; u++) {
        float hv = h[u];
#pragma unroll
        for (int oo = 0; oo < HH; oo++) o[oo] += hv * w2_s[u][oo];
    }

    const size_t bidx = (size_t)(p >> 18);      // p / (N*N)
    const size_t rem  = (size_t)(p & (NSQ - 1));
#pragma unroll
    for (int oo = 0; oo < HH; oo++)
        eb[(bidx * HH + oo) * (size_t)NSQ + rem] = o[oo];
}

// ---------------- fused attention per (b, h, 16-row tile) -----------------
// dynamic smem: q_s[16*64] | S[16*512] | kv[256*68]
#define KVSTRIDE 68
__global__ __launch_bounds__(256) void attn_kernel(
    const void* __restrict__ block_mask_raw,
    const void* __restrict__ pad_mask_raw,
    const float* __restrict__ ct_bias, const int* __restrict__ ct_idx,
    float* __restrict__ mean_out)
{
    extern __shared__ float smem[];
    float* q_s = smem;                  // 1024
    float* S   = smem + 1024;           // 8192
    float* kv  = smem + 1024 + 8192;    // 256*68 = 17408

    __shared__ unsigned char padi_s[16];
    __shared__ unsigned char padj_s[512];

    const int tid = threadIdx.x;
    const int idx = blockIdx.x;
    const int h  = idx & 7;
    const int it = (idx >> 3) & 31;
    const int b  = idx >> 8;
    const int i0 = it * 16;
    const int mode = g_mask_mode;

    const unsigned int*  bm_w = (const unsigned int*)block_mask_raw;
    const unsigned char* bm_b = (const unsigned char*)block_mask_raw;
    const unsigned int*  pm_w = (const unsigned int*)pad_mask_raw;
    const unsigned char* pm_b = (const unsigned char*)pad_mask_raw;

    // load q tile (16 rows x 64)
    {
        int r = tid >> 4, c4 = (tid & 15) * 4;
        float4 v = *(const float4*)&g_q[((size_t)(b * NN + i0 + r)) * HID + h * DD + c4];
        *(float4*)&q_s[r * 64 + c4] = v;
    }
    if (tid < 16) {
        int gi = b * NN + i0 + tid;
        padi_s[tid] = mode ? (pm_b[gi] != 0) : (pm_w[gi] != 0u);
    }
    for (int j = tid; j < 512; j += 256) {
        int gj = b * NN + j;
        padj_s[j] = mode ? (pm_b[gj] != 0) : (pm_w[gj] != 0u);
    }
    const float ctb = ct_bias[(size_t)ct_idx[b] * HH + h];
    __syncthreads();

    // prefill S with ct_bias + eb, or -inf where masked (vectorized)
    const size_t ebrow0 = ((size_t)(b * HH + h) * NN + i0) * NN;
    if (mode == 0) {
        for (int x = tid; x < 2048; x += 256) {
            int r = x >> 7, j4 = (x & 127) * 4;
            size_t gi = (size_t)(b * NN + i0 + r);
            uint4  mw  = *(const uint4*)&bm_w[gi * NN + j4];
            float4 ebv = *(const float4*)&g_eb[ebrow0 + (size_t)r * NN + j4];
            bool pi = padi_s[r];
            float4 sv;
            sv.x = (mw.x || pi || padj_s[j4 + 0]) ? -INFINITY : (ctb + ebv.x);
            sv.y = (mw.y || pi || padj_s[j4 + 1]) ? -INFINITY : (ctb + ebv.y);
            sv.z = (mw.z || pi || padj_s[j4 + 2]) ? -INFINITY : (ctb + ebv.z);
            sv.w = (mw.w || pi || padj_s[j4 + 3]) ? -INFINITY : (ctb + ebv.w);
            *(float4*)&S[r * 512 + j4] = sv;
        }
    } else {
        for (int x = tid; x < 2048; x += 256) {
            int r = x >> 7, j4 = (x & 127) * 4;
            size_t gi = (size_t)(b * NN + i0 + r);
            uchar4 mw  = *(const uchar4*)&bm_b[gi * NN + j4];
            float4 ebv = *(const float4*)&g_eb[ebrow0 + (size_t)r * NN + j4];
            bool pi = padi_s[r];
            float4 sv;
            sv.x = (mw.x || pi || padj_s[j4 + 0]) ? -INFINITY : (ctb + ebv.x);
            sv.y = (mw.y || pi || padj_s[j4 + 1]) ? -INFINITY : (ctb + ebv.y);
            sv.z = (mw.z || pi || padj_s[j4 + 2]) ? -INFINITY : (ctb + ebv.z);
            sv.w = (mw.w || pi || padj_s[j4 + 3]) ? -INFINITY : (ctb + ebv.w);
            *(float4*)&S[r * 512 + j4] = sv;
        }
    }
    __syncthreads();

    // ---- QK^T (float4 over d) ----
    {
        const int jx = tid & 63;
        const int ry = tid >> 6;
        for (int jt = 0; jt < 2; jt++) {
            for (int i = tid; i < 4096; i += 256) {
                int row = i >> 4, c4 = (i & 15) * 4;
                float4 v = *(const float4*)&g_k[((size_t)(b * NN + jt * 256 + row)) * HID + h * DD + c4];
                *(float4*)&kv[row * KVSTRIDE + c4] = v;
            }
            __syncthreads();
            float qacc[4][4];
#pragma unroll
            for (int i = 0; i < 4; i++)
#pragma unroll
                for (int j = 0; j < 4; j++) qacc[i][j] = 0.0f;
            for (int d0 = 0; d0 < 64; d0 += 4) {
                float4 qa[4], kb[4];
#pragma unroll
                for (int ri = 0; ri < 4; ri++)
                    qa[ri] = *(const float4*)&q_s[(ry + 4 * ri) * 64 + d0];
#pragma unroll
                for (int ji = 0; ji < 4; ji++)
                    kb[ji] = *(const float4*)&kv[(jx + 64 * ji) * KVSTRIDE + d0];
#pragma unroll
                for (int ri = 0; ri < 4; ri++)
#pragma unroll
                    for (int ji = 0; ji < 4; ji++)
                        qacc[ri][ji] += qa[ri].x * kb[ji].x + qa[ri].y * kb[ji].y
                                      + qa[ri].z * kb[ji].z + qa[ri].w * kb[ji].w;
            }
#pragma unroll
            for (int ri = 0; ri < 4; ri++)
#pragma unroll
                for (int ji = 0; ji < 4; ji++)
                    S[(ry + 4 * ri) * 512 + jt * 256 + jx + 64 * ji] += qacc[ri][ji] * 0.125f;
            __syncthreads();
        }
    }

    // ---- softmax + mean accumulation ----
    {
        const int warp = tid >> 5, lane = tid & 31;
        for (int r = warp; r < 16; r += 8) {
            float vals[16];
            float m = -INFINITY;
#pragma unroll
            for (int c = 0; c < 16; c++) {
                vals[c] = S[r * 512 + lane + 32 * c];
                m = fmaxf(m, vals[c]);
            }
#pragma unroll
            for (int off = 16; off; off >>= 1)
                m = fmaxf(m, __shfl_xor_sync(0xffffffffu, m, off));
            float sum = 0.0f;
            if (isinf(m) && m < 0.0f) {
#pragma unroll
                for (int c = 0; c < 16; c++) vals[c] = 0.0f;
            } else {
#pragma unroll
                for (int c = 0; c < 16; c++) { vals[c] = __expf(vals[c] - m); sum += vals[c]; }
            }
#pragma unroll
            for (int off = 16; off; off >>= 1)
                sum += __shfl_xor_sync(0xffffffffu, sum, off);
            float inv = (sum > 0.0f) ? (1.0f / sum) : 0.0f;
            size_t mrow = ((size_t)(b * NN + i0 + r)) * NN;
#pragma unroll
            for (int c = 0; c < 16; c++) {
                float pv = vals[c] * inv;
                S[r * 512 + lane + 32 * c] = pv;
                atomicAdd(&mean_out[mrow + lane + 32 * c], pv * 0.125f);
            }
        }
    }
    __syncthreads();

    // ---- P @ V (float4 over d) ----
    {
        const int g  = tid >> 6;
        const int t  = tid & 63;
        const int rx = t >> 4;
        const int dx = t & 15;          // d = dx*4 + di
        float oacc[4][4];
#pragma unroll
        for (int i = 0; i < 4; i++)
#pragma unroll
            for (int j = 0; j < 4; j++) oacc[i][j] = 0.0f;

        for (int jt = 0; jt < 2; jt++) {
            for (int i = tid; i < 4096; i += 256) {
                int row = i >> 4, c4 = (i & 15) * 4;
                float4 v = *(const float4*)&g_v[((size_t)(b * NN + jt * 256 + row)) * HID + h * DD + c4];
                *(float4*)&kv[row * KVSTRIDE + c4] = v;
            }
            __syncthreads();
            for (int jj = 0; jj < 64; jj++) {
                int j = g * 64 + jj;
                float4 vv = *(const float4*)&kv[j * KVSTRIDE + dx * 4];
                float pr[4];
#pragma unroll
                for (int ri = 0; ri < 4; ri++)
                    pr[ri] = S[(rx + 4 * ri) * 512 + jt * 256 + j];
#pragma unroll
                for (int ri = 0; ri < 4; ri++) {
                    oacc[ri][0] += pr[ri] * vv.x;
                    oacc[ri][1] += pr[ri] * vv.y;
                    oacc[ri][2] += pr[ri] * vv.z;
                    oacc[ri][3] += pr[ri] * vv.w;
                }
            }
            __syncthreads();
        }

        float* red = kv;  // 4*16*64 = 4096 floats
#pragma unroll
        for (int ri = 0; ri < 4; ri++)
            *(float4*)&red[(g * 16 + rx + 4 * ri) * 64 + dx * 4] =
                make_float4(oacc[ri][0], oacc[ri][1], oacc[ri][2], oacc[ri][3]);
        __syncthreads();
        for (int x = tid; x < 1024; x += 256) {
            int r = x >> 6, dc = x & 63;
            float v = red[r * 64 + dc] + red[1024 + r * 64 + dc]
                    + red[2048 + r * 64 + dc] + red[3072 + r * 64 + dc];
            g_ao[((size_t)(b * NN + i0 + r)) * HID + h * DD + dc] = v;
        }
    }
}

// ---------------- launch ----------------
extern "C" void kernel_launch(void* const* d_in, const int* in_sizes, int n_in,
                              void* d_out, int out_size)
{
    const float* x    = (const float*)d_in[0];
    const int*   ct   = (const int*)d_in[1];
    const float* ef   = (const float*)d_in[2];
    const void*  block_mask = d_in[3];
    const void*  pad_mask   = d_in[4];
    const float* Wq = (const float*)d_in[5];
    const float* bq = (const float*)d_in[6];
    const float* Wk = (const float*)d_in[7];
    const float* bk = (const float*)d_in[8];
    const float* Wv = (const float*)d_in[9];
    const float* bv = (const float*)d_in[10];
    const float* Wo = (const float*)d_in[11];
    const float* bo = (const float*)d_in[12];
    const float* We1 = (const float*)d_in[13];
    const float* be1 = (const float*)d_in[14];
    const float* We2 = (const float*)d_in[15];
    const float* be2 = (const float*)d_in[16];
    const float* ct_key  = (const float*)d_in[17];
    const float* ct_bias = (const float*)d_in[18];

    float* out_main = (float*)d_out;
    float* out_mean = out_main + OUT_PART;

    float *q_p, *k_p, *v_p, *ao_p, *eb_p;
    cudaGetSymbolAddress((void**)&q_p,  g_q);
    cudaGetSymbolAddress((void**)&k_p,  g_k);
    cudaGetSymbolAddress((void**)&v_p,  g_v);
    cudaGetSymbolAddress((void**)&ao_p, g_ao);
    cudaGetSymbolAddress((void**)&eb_p, g_eb);

    const int attn_smem = (1024 + 8192 + 256 * KVSTRIDE) * sizeof(float);
    cudaFuncSetAttribute(attn_kernel, cudaFuncAttributeMaxDynamicSharedMemorySize, attn_smem);

    // 0) detect mask element width
    detect_mask_kernel<<<1, 256>>>((const unsigned int*)block_mask);

    // 1) zero the mean output (accumulated via atomics)
    zero_kernel<<<(MEAN_ELEMS + 255) / 256, 256>>>(out_mean, MEAN_ELEMS);

    // 2) projections (fp16 tensor-core GEMM, fp32 accum)
    dim3 ggrid(512 / GBN, M_TOT / GBM);
    gemm_f16_kernel<<<ggrid, 256>>>(x, Wq, bq, ct_key, ct, q_p, 0);
    gemm_f16_kernel<<<ggrid, 256>>>(x, Wk, bk, ct_key, ct, k_p, 1);  // fuses +ct_key
    gemm_f16_kernel<<<ggrid, 256>>>(x, Wv, bv, ct_key, ct, v_p, 0);

    // 3) edge MLP (writes transposed (B,H,N,N))
    edge_mlp_kernel<<<(int)(PAIRS / 256), 256>>>(ef, We1, be1, We2, be2, eb_p);

    // 4) fused attention
    attn_kernel<<<BB * 32 * HH, 256, attn_smem>>>(block_mask, pad_mask, ct_bias, ct, out_mean);

    // 5) output projection
    gemm_f16_kernel<<<ggrid, 256>>>(ao_p, Wo, bo, ct_key, ct, out_main, 0);
}

// round 6
// speedup vs baseline: 2.9546x; 1.6025x over previous
#include <cuda_runtime.h>
#include <cuda_fp16.h>
#include <math.h>

// Problem constants
#define BB   8
#define NN   512
#define HID  512
#define HH   8
#define DD   64
#define EE   32
#define UU   16
#define M_TOT 4096
#define OUT_PART (BB * NN * HID)
#define NSQ  (NN * NN)
#define PAIRS ((long)BB * NN * NN)

// ---------------- scratch (device globals) ----------------
__device__ __half g_x16[M_TOT * HID];
__device__ __half g_wq16[HID * HID];
__device__ __half g_wk16[HID * HID];
__device__ __half g_wv16[HID * HID];
__device__ __half g_wo16[HID * HID];
__device__ __half g_q16[M_TOT * HID];
__device__ __half g_k16[M_TOT * HID];
__device__ __half g_v16[M_TOT * HID];
__device__ __half g_ao16[M_TOT * HID];
__device__ float  g_eb[BB * HH * NSQ];   // (B, H, N, N)
__device__ int    g_mask_mode;

// ---------------- fast exp on FMA pipe (MUFU is rt=8, the bottleneck) -----
__device__ __forceinline__ float fast_exp(float x) {
    float t = x * 1.44269504f;          // log2(e)
    t = fmaxf(t, -125.0f);              // handles -inf
    int   ei = __float2int_rn(t);
    float f  = t - __int2float_rn(ei);  // f in [-0.5, 0.5]
    float p  = 1.3333558e-3f;
    p = fmaf(p, f, 9.6181291e-3f);
    p = fmaf(p, f, 5.5504109e-2f);
    p = fmaf(p, f, 2.4022651e-1f);
    p = fmaf(p, f, 6.9314718e-1f);
    p = fmaf(p, f, 1.0f);
    return __int_as_float(__float_as_int(p) + (ei << 23));
}

// ---------------- mask dtype detection ----------------
__global__ void detect_mask_kernel(const unsigned int* __restrict__ bm) {
    __shared__ int sFloat, sHigh;
    if (threadIdx.x == 0) { sFloat = 0; sHigh = 0; }
    __syncthreads();
    unsigned int w = bm[threadIdx.x];
    if (w == 0x3F800000u) sFloat = 1;
    else if (w & 0xFFFFFF00u) sHigh = 1;
    __syncthreads();
    if (threadIdx.x == 0) g_mask_mode = (!sFloat && sHigh) ? 1 : 0;
}

// ---------------- fp32 -> fp16 convert ----------------
__global__ void f2h_kernel(const float* __restrict__ in, __half* __restrict__ out, int n4) {
    int i = blockIdx.x * blockDim.x + threadIdx.x;
    if (i < n4) {
        float4 v = ((const float4*)in)[i];
        ((__half2*)out)[2 * i]     = __float22half2_rn(make_float2(v.x, v.y));
        ((__half2*)out)[2 * i + 1] = __float22half2_rn(make_float2(v.z, v.w));
    }
}

// ---------------- mma helpers ----------------
__device__ __forceinline__ void ldmx4(unsigned& r0, unsigned& r1, unsigned& r2,
                                      unsigned& r3, const void* p) {
    unsigned a = (unsigned)__cvta_generic_to_shared(p);
    asm volatile("ldmatrix.sync.aligned.m8n8.x4.shared.b16 {%0,%1,%2,%3}, [%4];"
                 : "=r"(r0), "=r"(r1), "=r"(r2), "=r"(r3) : "r"(a));
}
__device__ __forceinline__ void ldmx4t(unsigned& r0, unsigned& r1, unsigned& r2,
                                       unsigned& r3, const void* p) {
    unsigned a = (unsigned)__cvta_generic_to_shared(p);
    asm volatile("ldmatrix.sync.aligned.m8n8.x4.trans.shared.b16 {%0,%1,%2,%3}, [%4];"
                 : "=r"(r0), "=r"(r1), "=r"(r2), "=r"(r3) : "r"(a));
}
__device__ __forceinline__ void ldmx2t(unsigned& r0, unsigned& r1, const void* p) {
    unsigned a = (unsigned)__cvta_generic_to_shared(p);
    asm volatile("ldmatrix.sync.aligned.m8n8.x2.trans.shared.b16 {%0,%1}, [%2];"
                 : "=r"(r0), "=r"(r1) : "r"(a));
}
__device__ __forceinline__ void mma16816(float* c, const unsigned* a,
                                         unsigned b0, unsigned b1) {
    asm volatile(
        "mma.sync.aligned.m16n8k16.row.col.f32.f16.f16.f32 "
        "{%0,%1,%2,%3}, {%4,%5,%6,%7}, {%8,%9}, {%0,%1,%2,%3};"
        : "+f"(c[0]), "+f"(c[1]), "+f"(c[2]), "+f"(c[3])
        : "r"(a[0]), "r"(a[1]), "r"(a[2]), "r"(a[3]), "r"(b0), "r"(b1));
}
__device__ __forceinline__ void cp16(void* sdst, const void* gsrc) {
    unsigned sa = (unsigned)__cvta_generic_to_shared(sdst);
    asm volatile("cp.async.ca.shared.global [%0], [%1], 16;" :: "r"(sa), "l"(gsrc));
}
__device__ __forceinline__ void cp_commit() { asm volatile("cp.async.commit_group;"); }

// ============ fp16 GEMM (double-buffered cp.async): C = A@W + bias (+ct) ==
// A,W fp16 row-major [*,512]. BM=128 BN=64 BK=32, 8 warps (4m x 2n).
#define GBM 128
#define GBN 64
#define GBK 32

__global__ __launch_bounds__(256) void gemm_f16_kernel(
    const __half* __restrict__ A, const __half* __restrict__ Bw,
    const float* __restrict__ bias,
    const float* __restrict__ ct_emb, const int* __restrict__ ct_idx,
    void* __restrict__ Cout, int add_ct, int out_f16)
{
    __shared__ __align__(16) __half As[2][GBM][GBK + 8];
    __shared__ __align__(16) __half Bs[2][GBK][GBN + 8];

    const int tid  = threadIdx.x;
    const int m0   = blockIdx.y * GBM;
    const int n0   = blockIdx.x * GBN;
    const int warp = tid >> 5, lane = tid & 31;
    const int wm   = warp >> 1, wn = warp & 1;

    float acc[2][4][4];
#pragma unroll
    for (int i = 0; i < 2; i++)
#pragma unroll
        for (int j = 0; j < 4; j++)
#pragma unroll
            for (int f = 0; f < 4; f++) acc[i][j][f] = 0.0f;

    const int arow = tid >> 2, ac8 = (tid & 3) * 8;
    const int brow = tid >> 3, bc8 = (tid & 7) * 8;

    {
        cp16(&As[0][arow][ac8],      &A[(size_t)(m0 + arow) * 512 + ac8]);
        cp16(&As[0][arow + 64][ac8], &A[(size_t)(m0 + arow + 64) * 512 + ac8]);
        cp16(&Bs[0][brow][bc8],      &Bw[(size_t)brow * 512 + n0 + bc8]);
        cp_commit();
    }

    for (int s = 0; s < 16; s++) {
        const int cur = s & 1;
        if (s < 15) {
            const int k0 = (s + 1) * GBK;
            cp16(&As[cur ^ 1][arow][ac8],      &A[(size_t)(m0 + arow) * 512 + k0 + ac8]);
            cp16(&As[cur ^ 1][arow + 64][ac8], &A[(size_t)(m0 + arow + 64) * 512 + k0 + ac8]);
            cp16(&Bs[cur ^ 1][brow][bc8],      &Bw[(size_t)(k0 + brow) * 512 + n0 + bc8]);
            cp_commit();
            asm volatile("cp.async.wait_group 1;");
        } else {
            asm volatile("cp.async.wait_group 0;");
        }
        __syncthreads();

#pragma unroll
        for (int ss = 0; ss < 2; ss++) {
            unsigned a[2][4], b[2][4];
#pragma unroll
            for (int mi = 0; mi < 2; mi++)
                ldmx4(a[mi][0], a[mi][1], a[mi][2], a[mi][3],
                      &As[cur][wm * 32 + mi * 16 + (lane & 15)][ss * 16 + (lane >> 4) * 8]);
#pragma unroll
            for (int p = 0; p < 2; p++)
                ldmx4t(b[p][0], b[p][1], b[p][2], b[p][3],
                       &Bs[cur][ss * 16 + ((lane >> 3) & 1) * 8 + (lane & 7)]
                              [wn * 32 + p * 16 + (lane >> 4) * 8]);
#pragma unroll
            for (int mi = 0; mi < 2; mi++)
#pragma unroll
                for (int nj = 0; nj < 4; nj++) {
                    int p = nj >> 1, hsel = nj & 1;
                    mma16816(acc[mi][nj], a[mi], b[p][2 * hsel], b[p][2 * hsel + 1]);
                }
        }
        __syncthreads();
    }

    // epilogue
#pragma unroll
    for (int mi = 0; mi < 2; mi++) {
        int row = m0 + wm * 32 + mi * 16 + (lane >> 2);
        const float* cte  = add_ct ? &ct_emb[(size_t)ct_idx[row >> 9] * 512] : nullptr;
        const float* cte2 = add_ct ? &ct_emb[(size_t)ct_idx[(row + 8) >> 9] * 512] : nullptr;
#pragma unroll
        for (int nj = 0; nj < 4; nj++) {
            int col = n0 + wn * 32 + nj * 8 + (lane & 3) * 2;
            float b0 = bias[col], b1 = bias[col + 1];
            float c0 = acc[mi][nj][0] + b0, c1 = acc[mi][nj][1] + b1;
            float c2 = acc[mi][nj][2] + b0, c3 = acc[mi][nj][3] + b1;
            if (add_ct) {
                c0 += cte[col];  c1 += cte[col + 1];
                c2 += cte2[col]; c3 += cte2[col + 1];
            }
            if (out_f16) {
                __half* C16 = (__half*)Cout;
                *(__half2*)&C16[(size_t)row * 512 + col]       = __float22half2_rn(make_float2(c0, c1));
                *(__half2*)&C16[(size_t)(row + 8) * 512 + col] = __float22half2_rn(make_float2(c2, c3));
            } else {
                float* Cf = (float*)Cout;
                *(float2*)&Cf[(size_t)row * 512 + col]       = make_float2(c0, c1);
                *(float2*)&Cf[(size_t)(row + 8) * 512 + col] = make_float2(c2, c3);
            }
        }
    }
}

// ---------------- edge MLP (HFMA2 stage1 + fast-exp ELU) ------------------
__global__ __launch_bounds__(256) void edge_mlp_kernel(
    const float* __restrict__ ef, const float* __restrict__ W1,
    const float* __restrict__ b1, const float* __restrict__ W2,
    const float* __restrict__ b2, float* __restrict__ eb)
{
    __shared__ __half2 w1h[EE][8];
    __shared__ float w2_s[UU][HH];
    __shared__ float b1_s[UU];
    __shared__ float b2_s[HH];

    const int tid = threadIdx.x;
    {
        int k = tid >> 3, u2 = tid & 7;   // 256 threads cover 32x8
        w1h[k][u2] = __float22half2_rn(make_float2(W1[k * 16 + 2 * u2], W1[k * 16 + 2 * u2 + 1]));
    }
    if (tid < UU * HH) ((float*)w2_s)[tid] = W2[tid];
    if (tid < UU) b1_s[tid] = b1[tid];
    if (tid < HH) b2_s[tid] = b2[tid];
    __syncthreads();

    const long p = (long)blockIdx.x * 256 + tid;

    float e[EE];
#pragma unroll
    for (int i = 0; i < EE / 4; i++) {
        float4 v = *(const float4*)&ef[p * EE + i * 4];
        e[i * 4 + 0] = v.x; e[i * 4 + 1] = v.y;
        e[i * 4 + 2] = v.z; e[i * 4 + 3] = v.w;
    }

    __half2 h2[8];
#pragma unroll
    for (int u = 0; u < 8; u++)
        h2[u] = __float22half2_rn(make_float2(b1_s[2 * u], b1_s[2 * u + 1]));
#pragma unroll
    for (int k = 0; k < EE; k++) {
        __half2 e2 = __float2half2_rn(e[k]);
#pragma unroll
        for (int u = 0; u < 8; u++) h2[u] = __hfma2(e2, w1h[k][u], h2[u]);
    }

    float o[HH];
#pragma unroll
    for (int oo = 0; oo < HH; oo++) o[oo] = b2_s[oo];
#pragma unroll
    for (int u = 0; u < 8; u++) {
        float2 hf = __half22float2(h2[u]);
        float ha = (hf.x > 0.0f) ? hf.x : (fast_exp(hf.x) - 1.0f);
        float hb = (hf.y > 0.0f) ? hf.y : (fast_exp(hf.y) - 1.0f);
#pragma unroll
        for (int oo = 0; oo < HH; oo++)
            o[oo] += ha * w2_s[2 * u][oo] + hb * w2_s[2 * u + 1][oo];
    }

    const size_t bidx = (size_t)(p >> 18);
    const size_t rem  = (size_t)(p & (NSQ - 1));
#pragma unroll
    for (int oo = 0; oo < HH; oo++)
        eb[(bidx * HH + oo) * (size_t)NSQ + rem] = o[oo];
}

// ---------------- fused attention: block per (b, 16-row tile), loop h -----
// dyn smem: S fp32 [16][520] | Pb fp16 [16][520] | kv fp16 [256][72] | qs fp16 [16][72]
#define SST 520
#define KVH 72
__global__ __launch_bounds__(256) void attn_kernel(
    const void* __restrict__ block_mask_raw,
    const void* __restrict__ pad_mask_raw,
    const float* __restrict__ ct_bias, const int* __restrict__ ct_idx,
    float* __restrict__ mean_out)
{
    extern __shared__ unsigned char dynsmem[];
    float*  S  = (float*)dynsmem;                                  // 33280 B
    __half* Pb = (__half*)(dynsmem + 33280);                       // 16640 B
    __half* kv = (__half*)(dynsmem + 33280 + 16640);               // 36864 B
    __half* qs = (__half*)(dynsmem + 33280 + 16640 + 36864);       // 2304 B

    __shared__ unsigned int maskbits[16][16];

    const int tid  = threadIdx.x;
    const int warp = tid >> 5, lane = tid & 31;
    const int b    = blockIdx.x >> 5;
    const int i0   = (blockIdx.x & 31) * 16;
    const int mode = g_mask_mode;

    const unsigned int*  bm_w = (const unsigned int*)block_mask_raw;
    const unsigned char* bm_b = (const unsigned char*)block_mask_raw;
    const unsigned int*  pm_w = (const unsigned int*)pad_mask_raw;
    const unsigned char* pm_b = (const unsigned char*)pad_mask_raw;

    // precompute combined mask bits once (bm | padi | padj)
    {
        int r = tid >> 4, w = tid & 15;
        size_t gi = (size_t)(b * NN + i0 + r);
        bool pi = mode ? (pm_b[gi] != 0) : (pm_w[gi] != 0u);
        unsigned int bits = 0;
        for (int k = 0; k < 32; k++) {
            int j = w * 32 + k;
            bool pj = mode ? (pm_b[b * NN + j] != 0) : (pm_w[b * NN + j] != 0u);
            bool bmv = mode ? (bm_b[gi * NN + j] != 0) : (bm_w[gi * NN + j] != 0u);
            if (bmv || pi || pj) bits |= (1u << k);
        }
        maskbits[r][w] = bits;
    }
    const int ctv = ct_idx[b];
    float mean_acc[2][16];
#pragma unroll
    for (int rr = 0; rr < 2; rr++)
#pragma unroll
        for (int c = 0; c < 16; c++) mean_acc[rr][c] = 0.0f;
    __syncthreads();

    for (int h = 0; h < HH; h++) {
        const float ctb = ct_bias[(size_t)ctv * HH + h];

        // ---- prefill S + load q ----
        const size_t ebrow0 = ((size_t)(b * HH + h) * NN + i0) * NN;
        for (int x = tid; x < 2048; x += 256) {
            int r = x >> 7, j4 = (x & 127) * 4;
            unsigned int bits = maskbits[r][j4 >> 5] >> (j4 & 31);
            float4 ebv = *(const float4*)&g_eb[ebrow0 + (size_t)r * NN + j4];
            float4 sv;
            sv.x = (bits & 1u) ? -INFINITY : (ctb + ebv.x);
            sv.y = (bits & 2u) ? -INFINITY : (ctb + ebv.y);
            sv.z = (bits & 4u) ? -INFINITY : (ctb + ebv.z);
            sv.w = (bits & 8u) ? -INFINITY : (ctb + ebv.w);
            *(float4*)&S[r * SST + j4] = sv;
        }
        if (tid < 128) {
            int row = tid >> 3, c8 = (tid & 7) * 8;
            *(uint4*)&qs[row * KVH + c8] =
                *(const uint4*)&g_q16[((size_t)(b * NN + i0 + row)) * HID + h * DD + c8];
        }
        __syncthreads();

        // q fragments (m16k16 x 4 k-steps)
        unsigned aq[4][4];
#pragma unroll
        for (int ks = 0; ks < 4; ks++)
            ldmx4(aq[ks][0], aq[ks][1], aq[ks][2], aq[ks][3],
                  &qs[(lane & 15) * KVH + ks * 16 + (lane >> 4) * 8]);

        // ---- QK^T ----
        for (int jt = 0; jt < 2; jt++) {
            for (int i = tid; i < 2048; i += 256) {
                int row = i >> 3, c8 = (i & 7) * 8;
                *(uint4*)&kv[row * KVH + c8] =
                    *(const uint4*)&g_k16[((size_t)(b * NN + jt * 256 + row)) * HID + h * DD + c8];
            }
            __syncthreads();

            float cacc[4][4];
#pragma unroll
            for (int i = 0; i < 4; i++)
#pragma unroll
                for (int j = 0; j < 4; j++) cacc[i][j] = 0.0f;

#pragma unroll
            for (int ks = 0; ks < 4; ks++) {
#pragma unroll
                for (int np = 0; np < 2; np++) {
                    unsigned r0, r1, r2, r3;
                    ldmx4(r0, r1, r2, r3,
                          &kv[(warp * 32 + np * 16 + ((lane >> 4) << 3) + (lane & 7)) * KVH
                              + ks * 16 + ((lane >> 3) & 1) * 8]);
                    mma16816(cacc[np * 2],     aq[ks], r0, r1);
                    mma16816(cacc[np * 2 + 1], aq[ks], r2, r3);
                }
            }
            int row0 = lane >> 2;
#pragma unroll
            for (int nt = 0; nt < 4; nt++) {
                int j = jt * 256 + warp * 32 + nt * 8 + (lane & 3) * 2;
                S[row0 * SST + j]           += cacc[nt][0] * 0.125f;
                S[row0 * SST + j + 1]       += cacc[nt][1] * 0.125f;
                S[(row0 + 8) * SST + j]     += cacc[nt][2] * 0.125f;
                S[(row0 + 8) * SST + j + 1] += cacc[nt][3] * 0.125f;
            }
            __syncthreads();
        }

        // ---- softmax + mean (FMA-pipe exp) ----
#pragma unroll
        for (int rr = 0; rr < 2; rr++) {
            int r = warp + rr * 8;
            float vals[16];
            float m = -INFINITY;
#pragma unroll
            for (int c = 0; c < 16; c++) {
                vals[c] = S[r * SST + lane + 32 * c];
                m = fmaxf(m, vals[c]);
            }
#pragma unroll
            for (int off = 16; off; off >>= 1)
                m = fmaxf(m, __shfl_xor_sync(0xffffffffu, m, off));
            float sum = 0.0f;
            if (m == -INFINITY) {
#pragma unroll
                for (int c = 0; c < 16; c++) vals[c] = 0.0f;
            } else {
#pragma unroll
                for (int c = 0; c < 16; c++) { vals[c] = fast_exp(vals[c] - m); sum += vals[c]; }
            }
#pragma unroll
            for (int off = 16; off; off >>= 1)
                sum += __shfl_xor_sync(0xffffffffu, sum, off);
            float inv = (sum > 0.0f) ? (1.0f / sum) : 0.0f;
#pragma unroll
            for (int c = 0; c < 16; c++) {
                float pv = vals[c] * inv;
                Pb[r * SST + lane + 32 * c] = __float2half(pv);
                mean_acc[rr][c] += pv;
            }
        }
        __syncthreads();

        // ---- P @ V ----
        float oacc[4] = {0.0f, 0.0f, 0.0f, 0.0f};
        const int d0 = warp * 8;
        for (int jt = 0; jt < 2; jt++) {
            for (int i = tid; i < 2048; i += 256) {
                int row = i >> 3, c8 = (i & 7) * 8;
                *(uint4*)&kv[row * KVH + c8] =
                    *(const uint4*)&g_v16[((size_t)(b * NN + jt * 256 + row)) * HID + h * DD + c8];
            }
            __syncthreads();
#pragma unroll
            for (int ks = 0; ks < 16; ks++) {
                unsigned ap0, ap1, ap2, ap3, v0, v1;
                ldmx4(ap0, ap1, ap2, ap3,
                      &Pb[(lane & 15) * SST + jt * 256 + ks * 16 + (lane >> 4) * 8]);
                ldmx2t(v0, v1, &kv[(ks * 16 + (lane & 15)) * KVH + d0]);
                unsigned ap[4] = {ap0, ap1, ap2, ap3};
                mma16816(oacc, ap, v0, v1);
            }
            __syncthreads();
        }
        {
            int row = lane >> 2, col = d0 + (lane & 3) * 2;
            __half* dst0 = &g_ao16[((size_t)(b * NN + i0 + row)) * HID + h * DD + col];
            __half* dst1 = &g_ao16[((size_t)(b * NN + i0 + row + 8)) * HID + h * DD + col];
            *(__half2*)dst0 = __float22half2_rn(make_float2(oacc[0], oacc[1]));
            *(__half2*)dst1 = __float22half2_rn(make_float2(oacc[2], oacc[3]));
        }
        __syncthreads();
    }

    // ---- write mean (no atomics) ----
#pragma unroll
    for (int rr = 0; rr < 2; rr++) {
        int row = i0 + warp + rr * 8;
        size_t base = ((size_t)(b * NN + row)) * NN;
#pragma unroll
        for (int c = 0; c < 16; c++)
            mean_out[base + lane + 32 * c] = mean_acc[rr][c] * 0.125f;
    }
}

// ---------------- launch ----------------
extern "C" void kernel_launch(void* const* d_in, const int* in_sizes, int n_in,
                              void* d_out, int out_size)
{
    const float* x    = (const float*)d_in[0];
    const int*   ct   = (const int*)d_in[1];
    const float* ef   = (const float*)d_in[2];
    const void*  block_mask = d_in[3];
    const void*  pad_mask   = d_in[4];
    const float* Wq = (const float*)d_in[5];
    const float* bq = (const float*)d_in[6];
    const float* Wk = (const float*)d_in[7];
    const float* bk = (const float*)d_in[8];
    const float* Wv = (const float*)d_in[9];
    const float* bv = (const float*)d_in[10];
    const float* Wo = (const float*)d_in[11];
    const float* bo = (const float*)d_in[12];
    const float* We1 = (const float*)d_in[13];
    const float* be1 = (const float*)d_in[14];
    const float* We2 = (const float*)d_in[15];
    const float* be2 = (const float*)d_in[16];
    const float* ct_key  = (const float*)d_in[17];
    const float* ct_bias = (const float*)d_in[18];

    float* out_main = (float*)d_out;
    float* out_mean = out_main + OUT_PART;

    __half *x16, *wq16, *wk16, *wv16, *wo16, *q16, *k16, *v16, *ao16;
    float* eb_p;
    cudaGetSymbolAddress((void**)&x16,  g_x16);
    cudaGetSymbolAddress((void**)&wq16, g_wq16);
    cudaGetSymbolAddress((void**)&wk16, g_wk16);
    cudaGetSymbolAddress((void**)&wv16, g_wv16);
    cudaGetSymbolAddress((void**)&wo16, g_wo16);
    cudaGetSymbolAddress((void**)&q16,  g_q16);
    cudaGetSymbolAddress((void**)&k16,  g_k16);
    cudaGetSymbolAddress((void**)&v16,  g_v16);
    cudaGetSymbolAddress((void**)&ao16, g_ao16);
    cudaGetSymbolAddress((void**)&eb_p, g_eb);

    const int attn_smem = 33280 + 16640 + 36864 + 2304;  // 89088
    cudaFuncSetAttribute(attn_kernel, cudaFuncAttributeMaxDynamicSharedMemorySize, attn_smem);

    // 0) mask dtype detect + fp16 conversions
    detect_mask_kernel<<<1, 256>>>((const unsigned int*)block_mask);
    f2h_kernel<<<(M_TOT * HID / 4 + 255) / 256, 256>>>(x, x16, M_TOT * HID / 4);
    f2h_kernel<<<(HID * HID / 4 + 255) / 256, 256>>>(Wq, wq16, HID * HID / 4);
    f2h_kernel<<<(HID * HID / 4 + 255) / 256, 256>>>(Wk, wk16, HID * HID / 4);
    f2h_kernel<<<(HID * HID / 4 + 255) / 256, 256>>>(Wv, wv16, HID * HID / 4);
    f2h_kernel<<<(HID * HID / 4 + 255) / 256, 256>>>(Wo, wo16, HID * HID / 4);

    // 1) projections (fp16 in, fp16 out)
    dim3 ggrid(512 / GBN, M_TOT / GBM);
    gemm_f16_kernel<<<ggrid, 256>>>(x16, wq16, bq, ct_key, ct, q16, 0, 1);
    gemm_f16_kernel<<<ggrid, 256>>>(x16, wk16, bk, ct_key, ct, k16, 1, 1);
    gemm_f16_kernel<<<ggrid, 256>>>(x16, wv16, bv, ct_key, ct, v16, 0, 1);

    // 2) edge MLP
    edge_mlp_kernel<<<(int)(PAIRS / 256), 256>>>(ef, We1, be1, We2, be2, eb_p);

    // 3) fused attention (writes ao16 + mean, no atomics)
    attn_kernel<<<BB * 32, 256, attn_smem>>>(block_mask, pad_mask, ct_bias, ct, out_mean);

    // 4) output projection (fp16 in, fp32 out)
    gemm_f16_kernel<<<ggrid, 256>>>(ao16, wo16, bo, ct_key, ct, out_main, 0, 0);
}

// round 10
// speedup vs baseline: 3.1371x; 1.0618x over previous
#include <cuda_runtime.h>
#include <cuda_fp16.h>
#include <math.h>

// Problem constants
#define BB   8
#define NN   512
#define HID  512
#define HH   8
#define DD   64
#define EE   32
#define UU   16
#define M_TOT 4096
#define OUT_PART (BB * NN * HID)
#define NSQ  (NN * NN)
#define PAIRS ((long)BB * NN * NN)

// ---------------- scratch (device globals) ----------------
__device__ __half g_x16[M_TOT * HID];
__device__ __half g_wq16[HID * HID];
__device__ __half g_wk16[HID * HID];
__device__ __half g_wv16[HID * HID];
__device__ __half g_wo16[HID * HID];
__device__ __half g_q16[M_TOT * HID];
__device__ __half g_k16[M_TOT * HID];
__device__ __half g_v16[M_TOT * HID];
__device__ __half g_ao16[M_TOT * HID];
__device__ __half g_eb16[BB * HH * NSQ];   // (B, H, N, N) fp16
__device__ int    g_mask_mode;

// ---------------- fast exp on FMA pipe ----------------
__device__ __forceinline__ float fast_exp(float x) {
    float t = x * 1.44269504f;
    t = fmaxf(t, -125.0f);
    int   ei = __float2int_rn(t);
    float f  = t - __int2float_rn(ei);
    float p  = 1.3333558e-3f;
    p = fmaf(p, f, 9.6181291e-3f);
    p = fmaf(p, f, 5.5504109e-2f);
    p = fmaf(p, f, 2.4022651e-1f);
    p = fmaf(p, f, 6.9314718e-1f);
    p = fmaf(p, f, 1.0f);
    return __int_as_float(__float_as_int(p) + (ei << 23));
}

// ---------------- mask dtype detection ----------------
__global__ void detect_mask_kernel(const unsigned int* __restrict__ bm) {
    __shared__ int sFloat, sHigh;
    if (threadIdx.x == 0) { sFloat = 0; sHigh = 0; }
    __syncthreads();
    unsigned int w = bm[threadIdx.x];
    if (w == 0x3F800000u) sFloat = 1;
    else if (w & 0xFFFFFF00u) sHigh = 1;
    __syncthreads();
    if (threadIdx.x == 0) g_mask_mode = (!sFloat && sHigh) ? 1 : 0;
}

// ---------------- fused fp32 -> fp16 convert (x + 4 weights) --------------
#define XF4 (M_TOT * HID / 4)      // 524288
#define WF4 (HID * HID / 4)        // 65536
__global__ void convert_all_kernel(const float* __restrict__ x,
                                   const float* __restrict__ Wq,
                                   const float* __restrict__ Wk,
                                   const float* __restrict__ Wv,
                                   const float* __restrict__ Wo) {
    int i = blockIdx.x * blockDim.x + threadIdx.x;
    const float* src; __half* dst; int off;
    if (i < XF4) { src = x; dst = g_x16; off = i; }
    else {
        int r = i - XF4;
        int seg = r >> 16;           // / 65536
        off = r & 65535;
        switch (seg) {
            case 0: src = Wq; dst = g_wq16; break;
            case 1: src = Wk; dst = g_wk16; break;
            case 2: src = Wv; dst = g_wv16; break;
            default: src = Wo; dst = g_wo16; break;
        }
    }
    float4 v = ((const float4*)src)[off];
    ((__half2*)dst)[2 * off]     = __float22half2_rn(make_float2(v.x, v.y));
    ((__half2*)dst)[2 * off + 1] = __float22half2_rn(make_float2(v.z, v.w));
}
#define CONV_TOT (XF4 + 4 * WF4)

// ---------------- mma helpers ----------------
__device__ __forceinline__ void ldmx4(unsigned& r0, unsigned& r1, unsigned& r2,
                                      unsigned& r3, const void* p) {
    unsigned a = (unsigned)__cvta_generic_to_shared(p);
    asm volatile("ldmatrix.sync.aligned.m8n8.x4.shared.b16 {%0,%1,%2,%3}, [%4];"
                 : "=r"(r0), "=r"(r1), "=r"(r2), "=r"(r3) : "r"(a));
}
__device__ __forceinline__ void ldmx4t(unsigned& r0, unsigned& r1, unsigned& r2,
                                       unsigned& r3, const void* p) {
    unsigned a = (unsigned)__cvta_generic_to_shared(p);
    asm volatile("ldmatrix.sync.aligned.m8n8.x4.trans.shared.b16 {%0,%1,%2,%3}, [%4];"
                 : "=r"(r0), "=r"(r1), "=r"(r2), "=r"(r3) : "r"(a));
}
__device__ __forceinline__ void ldmx2t(unsigned& r0, unsigned& r1, const void* p) {
    unsigned a = (unsigned)__cvta_generic_to_shared(p);
    asm volatile("ldmatrix.sync.aligned.m8n8.x2.trans.shared.b16 {%0,%1}, [%2];"
                 : "=r"(r0), "=r"(r1) : "r"(a));
}
__device__ __forceinline__ void mma16816(float* c, const unsigned* a,
                                         unsigned b0, unsigned b1) {
    asm volatile(
        "mma.sync.aligned.m16n8k16.row.col.f32.f16.f16.f32 "
        "{%0,%1,%2,%3}, {%4,%5,%6,%7}, {%8,%9}, {%0,%1,%2,%3};"
        : "+f"(c[0]), "+f"(c[1]), "+f"(c[2]), "+f"(c[3])
        : "r"(a[0]), "r"(a[1]), "r"(a[2]), "r"(a[3]), "r"(b0), "r"(b1));
}
__device__ __forceinline__ void cp16(void* sdst, const void* gsrc) {
    unsigned sa = (unsigned)__cvta_generic_to_shared(sdst);
    asm volatile("cp.async.ca.shared.global [%0], [%1], 16;" :: "r"(sa), "l"(gsrc));
}
__device__ __forceinline__ void cp_commit() { asm volatile("cp.async.commit_group;"); }

// ============ fp16 GEMM (double-buffered cp.async) ==========
#define GBM 128
#define GBN 64
#define GBK 32

__global__ __launch_bounds__(256) void gemm_f16_kernel(
    const __half* __restrict__ A, const __half* __restrict__ Bw,
    const float* __restrict__ bias,
    const float* __restrict__ ct_emb, const int* __restrict__ ct_idx,
    void* __restrict__ Cout, int add_ct, int out_f16)
{
    __shared__ __align__(16) __half As[2][GBM][GBK + 8];
    __shared__ __align__(16) __half Bs[2][GBK][GBN + 8];

    const int tid  = threadIdx.x;
    const int m0   = blockIdx.y * GBM;
    const int n0   = blockIdx.x * GBN;
    const int warp = tid >> 5, lane = tid & 31;
    const int wm   = warp >> 1, wn = warp & 1;

    float acc[2][4][4];
#pragma unroll
    for (int i = 0; i < 2; i++)
#pragma unroll
        for (int j = 0; j < 4; j++)
#pragma unroll
            for (int f = 0; f < 4; f++) acc[i][j][f] = 0.0f;

    const int arow = tid >> 2, ac8 = (tid & 3) * 8;
    const int brow = tid >> 3, bc8 = (tid & 7) * 8;

    {
        cp16(&As[0][arow][ac8],      &A[(size_t)(m0 + arow) * 512 + ac8]);
        cp16(&As[0][arow + 64][ac8], &A[(size_t)(m0 + arow + 64) * 512 + ac8]);
        cp16(&Bs[0][brow][bc8],      &Bw[(size_t)brow * 512 + n0 + bc8]);
        cp_commit();
    }

    for (int s = 0; s < 16; s++) {
        const int cur = s & 1;
        if (s < 15) {
            const int k0 = (s + 1) * GBK;
            cp16(&As[cur ^ 1][arow][ac8],      &A[(size_t)(m0 + arow) * 512 + k0 + ac8]);
            cp16(&As[cur ^ 1][arow + 64][ac8], &A[(size_t)(m0 + arow + 64) * 512 + k0 + ac8]);
            cp16(&Bs[cur ^ 1][brow][bc8],      &Bw[(size_t)(k0 + brow) * 512 + n0 + bc8]);
            cp_commit();
            asm volatile("cp.async.wait_group 1;");
        } else {
            asm volatile("cp.async.wait_group 0;");
        }
        __syncthreads();

#pragma unroll
        for (int ss = 0; ss < 2; ss++) {
            unsigned a[2][4], b[2][4];
#pragma unroll
            for (int mi = 0; mi < 2; mi++)
                ldmx4(a[mi][0], a[mi][1], a[mi][2], a[mi][3],
                      &As[cur][wm * 32 + mi * 16 + (lane & 15)][ss * 16 + (lane >> 4) * 8]);
#pragma unroll
            for (int p = 0; p < 2; p++)
                ldmx4t(b[p][0], b[p][1], b[p][2], b[p][3],
                       &Bs[cur][ss * 16 + ((lane >> 3) & 1) * 8 + (lane & 7)]
                              [wn * 32 + p * 16 + (lane >> 4) * 8]);
#pragma unroll
            for (int mi = 0; mi < 2; mi++)
#pragma unroll
                for (int nj = 0; nj < 4; nj++) {
                    int p = nj >> 1, hsel = nj & 1;
                    mma16816(acc[mi][nj], a[mi], b[p][2 * hsel], b[p][2 * hsel + 1]);
                }
        }
        __syncthreads();
    }

#pragma unroll
    for (int mi = 0; mi < 2; mi++) {
        int row = m0 + wm * 32 + mi * 16 + (lane >> 2);
        const float* cte  = add_ct ? &ct_emb[(size_t)ct_idx[row >> 9] * 512] : nullptr;
        const float* cte2 = add_ct ? &ct_emb[(size_t)ct_idx[(row + 8) >> 9] * 512] : nullptr;
#pragma unroll
        for (int nj = 0; nj < 4; nj++) {
            int col = n0 + wn * 32 + nj * 8 + (lane & 3) * 2;
            float b0 = bias[col], b1 = bias[col + 1];
            float c0 = acc[mi][nj][0] + b0, c1 = acc[mi][nj][1] + b1;
            float c2 = acc[mi][nj][2] + b0, c3 = acc[mi][nj][3] + b1;
            if (add_ct) {
                c0 += cte[col];  c1 += cte[col + 1];
                c2 += cte2[col]; c3 += cte2[col + 1];
            }
            if (out_f16) {
                __half* C16 = (__half*)Cout;
                *(__half2*)&C16[(size_t)row * 512 + col]       = __float22half2_rn(make_float2(c0, c1));
                *(__half2*)&C16[(size_t)(row + 8) * 512 + col] = __float22half2_rn(make_float2(c2, c3));
            } else {
                float* Cf = (float*)Cout;
                *(float2*)&Cf[(size_t)row * 512 + col]       = make_float2(c0, c1);
                *(float2*)&Cf[(size_t)(row + 8) * 512 + col] = make_float2(c2, c3);
            }
        }
    }
}

// ---------------- edge MLP (HFMA2 stage1 + fast-exp ELU, fp16 out) --------
__global__ __launch_bounds__(256) void edge_mlp_kernel(
    const float* __restrict__ ef, const float* __restrict__ W1,
    const float* __restrict__ b1, const float* __restrict__ W2,
    const float* __restrict__ b2)
{
    __shared__ __half2 w1h[EE][8];
    __shared__ float w2_s[UU][HH];
    __shared__ float b1_s[UU];
    __shared__ float b2_s[HH];

    const int tid = threadIdx.x;
    {
        int k = tid >> 3, u2 = tid & 7;
        w1h[k][u2] = __float22half2_rn(make_float2(W1[k * 16 + 2 * u2], W1[k * 16 + 2 * u2 + 1]));
    }
    if (tid < UU * HH) ((float*)w2_s)[tid] = W2[tid];
    if (tid < UU) b1_s[tid] = b1[tid];
    if (tid < HH) b2_s[tid] = b2[tid];
    __syncthreads();

    const long p = (long)blockIdx.x * 256 + tid;

    float e[EE];
#pragma unroll
    for (int i = 0; i < EE / 4; i++) {
        float4 v = *(const float4*)&ef[p * EE + i * 4];
        e[i * 4 + 0] = v.x; e[i * 4 + 1] = v.y;
        e[i * 4 + 2] = v.z; e[i * 4 + 3] = v.w;
    }

    __half2 h2[8];
#pragma unroll
    for (int u = 0; u < 8; u++)
        h2[u] = __float22half2_rn(make_float2(b1_s[2 * u], b1_s[2 * u + 1]));
#pragma unroll
    for (int k = 0; k < EE; k++) {
        __half2 e2 = __float2half2_rn(e[k]);
#pragma unroll
        for (int u = 0; u < 8; u++) h2[u] = __hfma2(e2, w1h[k][u], h2[u]);
    }

    float o[HH];
#pragma unroll
    for (int oo = 0; oo < HH; oo++) o[oo] = b2_s[oo];
#pragma unroll
    for (int u = 0; u < 8; u++) {
        float2 hf = __half22float2(h2[u]);
        float ha = (hf.x > 0.0f) ? hf.x : (fast_exp(hf.x) - 1.0f);
        float hb = (hf.y > 0.0f) ? hf.y : (fast_exp(hf.y) - 1.0f);
#pragma unroll
        for (int oo = 0; oo < HH; oo++)
            o[oo] += ha * w2_s[2 * u][oo] + hb * w2_s[2 * u + 1][oo];
    }

    const size_t bidx = (size_t)(p >> 18);
    const size_t rem  = (size_t)(p & (NSQ - 1));
#pragma unroll
    for (int oo = 0; oo < HH; oo++)
        g_eb16[(bidx * HH + oo) * (size_t)NSQ + rem] = __float2half_rn(o[oo]);
}

// ---------------- fused attention (ct_bias dropped: softmax-invariant) ----
#define SST 520
#define KVH 72
__global__ __launch_bounds__(256) void attn_kernel(
    const void* __restrict__ block_mask_raw,
    const void* __restrict__ pad_mask_raw,
    float* __restrict__ mean_out)
{
    extern __shared__ unsigned char dynsmem[];
    float*  S  = (float*)dynsmem;                                  // 33280 B
    __half* Pb = (__half*)(dynsmem + 33280);                       // 16640 B
    __half* kv = (__half*)(dynsmem + 33280 + 16640);               // 36864 B
    __half* qs = (__half*)(dynsmem + 33280 + 16640 + 36864);       // 2304 B

    __shared__ unsigned int maskbits[16][16];

    const int tid  = threadIdx.x;
    const int warp = tid >> 5, lane = tid & 31;
    const int b    = blockIdx.x >> 5;
    const int i0   = (blockIdx.x & 31) * 16;
    const int mode = g_mask_mode;

    const unsigned int*  bm_w = (const unsigned int*)block_mask_raw;
    const unsigned char* bm_b = (const unsigned char*)block_mask_raw;
    const unsigned int*  pm_w = (const unsigned int*)pad_mask_raw;
    const unsigned char* pm_b = (const unsigned char*)pad_mask_raw;

    // combined mask bits (bm | padi | padj), decoded once
    {
        int r = tid >> 4, w = tid & 15;
        size_t gi = (size_t)(b * NN + i0 + r);
        bool pi = mode ? (pm_b[gi] != 0) : (pm_w[gi] != 0u);
        unsigned int bits = 0;
        for (int k = 0; k < 32; k++) {
            int j = w * 32 + k;
            bool pj = mode ? (pm_b[b * NN + j] != 0) : (pm_w[b * NN + j] != 0u);
            bool bmv = mode ? (bm_b[gi * NN + j] != 0) : (bm_w[gi * NN + j] != 0u);
            if (bmv || pi || pj) bits |= (1u << k);
        }
        maskbits[r][w] = bits;
    }
    float mean_acc[2][16];
#pragma unroll
    for (int rr = 0; rr < 2; rr++)
#pragma unroll
        for (int c = 0; c < 16; c++) mean_acc[rr][c] = 0.0f;
    __syncthreads();

    for (int h = 0; h < HH; h++) {
        // ---- prefill S with eb (fp16) / -inf ----
        const size_t ebrow0 = ((size_t)(b * HH + h) * NN + i0) * NN;
        for (int x = tid; x < 1024; x += 256) {
            int r = x >> 6, j8 = (x & 63) * 8;
            unsigned int bits = maskbits[r][j8 >> 5] >> (j8 & 31);
            uint4 raw = *(const uint4*)&g_eb16[ebrow0 + (size_t)r * NN + j8];
            __half2* hp = (__half2*)&raw;
            float2 f0 = __half22float2(hp[0]);
            float2 f1 = __half22float2(hp[1]);
            float2 f2 = __half22float2(hp[2]);
            float2 f3 = __half22float2(hp[3]);
            float4 s0, s1;
            s0.x = (bits &   1u) ? -INFINITY : f0.x;
            s0.y = (bits &   2u) ? -INFINITY : f0.y;
            s0.z = (bits &   4u) ? -INFINITY : f1.x;
            s0.w = (bits &   8u) ? -INFINITY : f1.y;
            s1.x = (bits &  16u) ? -INFINITY : f2.x;
            s1.y = (bits &  32u) ? -INFINITY : f2.y;
            s1.z = (bits &  64u) ? -INFINITY : f3.x;
            s1.w = (bits & 128u) ? -INFINITY : f3.y;
            *(float4*)&S[r * SST + j8]     = s0;
            *(float4*)&S[r * SST + j8 + 4] = s1;
        }
        if (tid < 128) {
            int row = tid >> 3, c8 = (tid & 7) * 8;
            *(uint4*)&qs[row * KVH + c8] =
                *(const uint4*)&g_q16[((size_t)(b * NN + i0 + row)) * HID + h * DD + c8];
        }
        __syncthreads();

        unsigned aq[4][4];
#pragma unroll
        for (int ks = 0; ks < 4; ks++)
            ldmx4(aq[ks][0], aq[ks][1], aq[ks][2], aq[ks][3],
                  &qs[(lane & 15) * KVH + ks * 16 + (lane >> 4) * 8]);

        // ---- QK^T ----
        for (int jt = 0; jt < 2; jt++) {
            for (int i = tid; i < 2048; i += 256) {
                int row = i >> 3, c8 = (i & 7) * 8;
                *(uint4*)&kv[row * KVH + c8] =
                    *(const uint4*)&g_k16[((size_t)(b * NN + jt * 256 + row)) * HID + h * DD + c8];
            }
            __syncthreads();

            float cacc[4][4];
#pragma unroll
            for (int i = 0; i < 4; i++)
#pragma unroll
                for (int j = 0; j < 4; j++) cacc[i][j] = 0.0f;

#pragma unroll
            for (int ks = 0; ks < 4; ks++) {
#pragma unroll
                for (int np = 0; np < 2; np++) {
                    unsigned r0, r1, r2, r3;
                    ldmx4(r0, r1, r2, r3,
                          &kv[(warp * 32 + np * 16 + ((lane >> 4) << 3) + (lane & 7)) * KVH
                              + ks * 16 + ((lane >> 3) & 1) * 8]);
                    mma16816(cacc[np * 2],     aq[ks], r0, r1);
                    mma16816(cacc[np * 2 + 1], aq[ks], r2, r3);
                }
            }
            int row0 = lane >> 2;
#pragma unroll
            for (int nt = 0; nt < 4; nt++) {
                int j = jt * 256 + warp * 32 + nt * 8 + (lane & 3) * 2;
                S[row0 * SST + j]           += cacc[nt][0] * 0.125f;
                S[row0 * SST + j + 1]       += cacc[nt][1] * 0.125f;
                S[(row0 + 8) * SST + j]     += cacc[nt][2] * 0.125f;
                S[(row0 + 8) * SST + j + 1] += cacc[nt][3] * 0.125f;
            }
            __syncthreads();
        }

        // ---- softmax + mean (FMA-pipe exp) ----
#pragma unroll
        for (int rr = 0; rr < 2; rr++) {
            int r = warp + rr * 8;
            float vals[16];
            float m = -INFINITY;
#pragma unroll
            for (int c = 0; c < 16; c++) {
                vals[c] = S[r * SST + lane + 32 * c];
                m = fmaxf(m, vals[c]);
            }
#pragma unroll
            for (int off = 16; off; off >>= 1)
                m = fmaxf(m, __shfl_xor_sync(0xffffffffu, m, off));
            float sum = 0.0f;
            if (m == -INFINITY) {
#pragma unroll
                for (int c = 0; c < 16; c++) vals[c] = 0.0f;
            } else {
#pragma unroll
                for (int c = 0; c < 16; c++) { vals[c] = fast_exp(vals[c] - m); sum += vals[c]; }
            }
#pragma unroll
            for (int off = 16; off; off >>= 1)
                sum += __shfl_xor_sync(0xffffffffu, sum, off);
            float inv = (sum > 0.0f) ? (1.0f / sum) : 0.0f;
#pragma unroll
            for (int c = 0; c < 16; c++) {
                float pv = vals[c] * inv;
                Pb[r * SST + lane + 32 * c] = __float2half(pv);
                mean_acc[rr][c] += pv;
            }
        }
        __syncthreads();

        // ---- P @ V ----
        float oacc[4] = {0.0f, 0.0f, 0.0f, 0.0f};
        const int d0 = warp * 8;
        for (int jt = 0; jt < 2; jt++) {
            for (int i = tid; i < 2048; i += 256) {
                int row = i >> 3, c8 = (i & 7) * 8;
                *(uint4*)&kv[row * KVH + c8] =
                    *(const uint4*)&g_v16[((size_t)(b * NN + jt * 256 + row)) * HID + h * DD + c8];
            }
            __syncthreads();
#pragma unroll
            for (int ks = 0; ks < 16; ks++) {
                unsigned ap0, ap1, ap2, ap3, v0, v1;
                ldmx4(ap0, ap1, ap2, ap3,
                      &Pb[(lane & 15) * SST + jt * 256 + ks * 16 + (lane >> 4) * 8]);
                ldmx2t(v0, v1, &kv[(ks * 16 + (lane & 15)) * KVH + d0]);
                unsigned ap[4] = {ap0, ap1, ap2, ap3};
                mma16816(oacc, ap, v0, v1);
            }
            __syncthreads();
        }
        {
            int row = lane >> 2, col = d0 + (lane & 3) * 2;
            __half* dst0 = &g_ao16[((size_t)(b * NN + i0 + row)) * HID + h * DD + col];
            __half* dst1 = &g_ao16[((size_t)(b * NN + i0 + row + 8)) * HID + h * DD + col];
            *(__half2*)dst0 = __float22half2_rn(make_float2(oacc[0], oacc[1]));
            *(__half2*)dst1 = __float22half2_rn(make_float2(oacc[2], oacc[3]));
        }
        __syncthreads();
    }

    // ---- write mean ----
#pragma unroll
    for (int rr = 0; rr < 2; rr++) {
        int row = i0 + warp + rr * 8;
        size_t base = ((size_t)(b * NN + row)) * NN;
#pragma unroll
        for (int c = 0; c < 16; c++)
            mean_out[base + lane + 32 * c] = mean_acc[rr][c] * 0.125f;
    }
}

// ---------------- stream/event context (created once at load) -------------
struct OverlapCtx {
    cudaStream_t s2 = nullptr;
    cudaEvent_t  e1 = nullptr, e2 = nullptr;
    bool ok = false;
    OverlapCtx() {
        ok = (cudaStreamCreateWithFlags(&s2, cudaStreamNonBlocking) == cudaSuccess) &&
             (cudaEventCreateWithFlags(&e1, cudaEventDisableTiming) == cudaSuccess) &&
             (cudaEventCreateWithFlags(&e2, cudaEventDisableTiming) == cudaSuccess);
    }
};
static OverlapCtx g_ovl;

// ---------------- launch ----------------
extern "C" void kernel_launch(void* const* d_in, const int* in_sizes, int n_in,
                              void* d_out, int out_size)
{
    const float* x    = (const float*)d_in[0];
    const int*   ct   = (const int*)d_in[1];
    const float* ef   = (const float*)d_in[2];
    const void*  block_mask = d_in[3];
    const void*  pad_mask   = d_in[4];
    const float* Wq = (const float*)d_in[5];
    const float* bq = (const float*)d_in[6];
    const float* Wk = (const float*)d_in[7];
    const float* bk = (const float*)d_in[8];
    const float* Wv = (const float*)d_in[9];
    const float* bv = (const float*)d_in[10];
    const float* Wo = (const float*)d_in[11];
    const float* bo = (const float*)d_in[12];
    const float* We1 = (const float*)d_in[13];
    const float* be1 = (const float*)d_in[14];
    const float* We2 = (const float*)d_in[15];
    const float* be2 = (const float*)d_in[16];
    const float* ct_key  = (const float*)d_in[17];

    float* out_main = (float*)d_out;
    float* out_mean = out_main + OUT_PART;

    __half *x16, *wq16, *wk16, *wv16, *wo16, *q16, *k16, *v16, *ao16;
    cudaGetSymbolAddress((void**)&x16,  g_x16);
    cudaGetSymbolAddress((void**)&wq16, g_wq16);
    cudaGetSymbolAddress((void**)&wk16, g_wk16);
    cudaGetSymbolAddress((void**)&wv16, g_wv16);
    cudaGetSymbolAddress((void**)&wo16, g_wo16);
    cudaGetSymbolAddress((void**)&q16,  g_q16);
    cudaGetSymbolAddress((void**)&k16,  g_k16);
    cudaGetSymbolAddress((void**)&v16,  g_v16);
    cudaGetSymbolAddress((void**)&ao16, g_ao16);

    const int attn_smem = 33280 + 16640 + 36864 + 2304;  // 89088
    cudaFuncSetAttribute(attn_kernel, cudaFuncAttributeMaxDynamicSharedMemorySize, attn_smem);

    const bool ovl = g_ovl.ok;

    // 0) mask dtype detect (main stream)
    detect_mask_kernel<<<1, 256>>>((const unsigned int*)block_mask);

    // fork: edge MLP on side stream (DRAM-bound) overlaps projections (tensor-bound)
    if (ovl) {
        cudaEventRecord(g_ovl.e1, 0);
        cudaStreamWaitEvent(g_ovl.s2, g_ovl.e1, 0);
        edge_mlp_kernel<<<(int)(PAIRS / 256), 256, 0, g_ovl.s2>>>(ef, We1, be1, We2, be2);
        cudaEventRecord(g_ovl.e2, g_ovl.s2);
    }

    // 1) fused fp16 conversions + projections (main stream)
    convert_all_kernel<<<(CONV_TOT + 255) / 256, 256>>>(x, Wq, Wk, Wv, Wo);
    dim3 ggrid(512 / GBN, M_TOT / GBM);
    gemm_f16_kernel<<<ggrid, 256>>>(x16, wq16, bq, ct_key, ct, q16, 0, 1);
    gemm_f16_kernel<<<ggrid, 256>>>(x16, wk16, bk, ct_key, ct, k16, 1, 1);
    gemm_f16_kernel<<<ggrid, 256>>>(x16, wv16, bv, ct_key, ct, v16, 0, 1);

    if (ovl) {
        cudaStreamWaitEvent(0, g_ovl.e2, 0);   // join edge before attn
    } else {
        edge_mlp_kernel<<<(int)(PAIRS / 256), 256>>>(ef, We1, be1, We2, be2);
    }

    // 3) fused attention
    attn_kernel<<<BB * 32, 256, attn_smem>>>(block_mask, pad_mask, out_mean);

    // 4) output projection
    gemm_f16_kernel<<<ggrid, 256>>>(ao16, wo16, bo, ct_key, ct, out_main, 0, 0);
}